// round 6
// baseline (speedup 1.0000x reference)
#include <cuda_runtime.h>
#include <cuda_fp16.h>
#include <cstdint>
#include <math.h>

#define HW 4096
#define NC 128

// Scratch (static device memory — no allocations allowed)
__device__ float  g_xn[2][NC * HW];        // normalized inputs (residual), fp32
__device__ __half g_qkv[2][3 * NC * HW];   // qkv projections [384][4096], fp16 (Q prescaled)
__device__ __half g_o[2][NC * HW];         // attention outputs [128][4096], fp16
__device__ __half g_wh[2][NC * NC];        // outproj weights fp16 (preconverted)
__device__ float2 g_gnp[2][16][8];         // groupnorm partial sums

// 1/sqrt(128) * log2(e): folded into Q so softmax is a bare ex2
#define QSCALE (0.08838834764831845f * 1.4426950408889634f)

// ---------------------------------------------------------------------------
// helpers
// ---------------------------------------------------------------------------
__device__ __forceinline__ uint32_t s2u(const void* p) {
    uint32_t a;
    asm("{ .reg .u64 t; cvta.to.shared.u64 t, %1; cvt.u32.u64 %0, t; }" : "=r"(a) : "l"(p));
    return a;
}
__device__ __forceinline__ void mma16816(float* c, const uint32_t* a, uint32_t b0, uint32_t b1) {
    asm volatile(
        "mma.sync.aligned.m16n8k16.row.col.f32.f16.f16.f32 "
        "{%0,%1,%2,%3}, {%4,%5,%6,%7}, {%8,%9}, {%0,%1,%2,%3};"
        : "+f"(c[0]), "+f"(c[1]), "+f"(c[2]), "+f"(c[3])
        : "r"(a[0]), "r"(a[1]), "r"(a[2]), "r"(a[3]), "r"(b0), "r"(b1));
}
// fp16-accumulate variant: C fragment {c0c1},{c2c3} == P A-fragment packing
__device__ __forceinline__ void mma16816h(uint32_t* c, const uint32_t* a, uint32_t b0, uint32_t b1) {
    asm volatile(
        "mma.sync.aligned.m16n8k16.row.col.f16.f16.f16.f16 "
        "{%0,%1}, {%2,%3,%4,%5}, {%6,%7}, {%0,%1};"
        : "+r"(c[0]), "+r"(c[1])
        : "r"(a[0]), "r"(a[1]), "r"(a[2]), "r"(a[3]), "r"(b0), "r"(b1));
}
#define LDSM_T(r, p) \
    asm volatile("ldmatrix.sync.aligned.m8n8.x4.trans.shared.b16 {%0,%1,%2,%3}, [%4];" \
        : "=r"((r)[0]), "=r"((r)[1]), "=r"((r)[2]), "=r"((r)[3]) : "r"(p))
#define LDSM_N(r, p) \
    asm volatile("ldmatrix.sync.aligned.m8n8.x4.shared.b16 {%0,%1,%2,%3}, [%4];" \
        : "=r"((r)[0]), "=r"((r)[1]), "=r"((r)[2]), "=r"((r)[3]) : "r"(p))
#define CP16(dst, src) \
    asm volatile("cp.async.cg.shared.global [%0], [%1], 16;" :: "r"(dst), "l"(src))

// ---------------------------------------------------------------------------
// GroupNorm pass A: partial sums. grid (16 g, 8 s, 2 t), 256 threads.
// ---------------------------------------------------------------------------
__global__ void gnA_kernel(const float* __restrict__ xA, const float* __restrict__ xB) {
    int g = blockIdx.x, s = blockIdx.y, t = blockIdx.z, tid = threadIdx.x;
    const float4* xs = (const float4*)((t ? xB : xA) + g * 32768 + s * 4096);
    float sm = 0.f, sq = 0.f;
    for (int i = tid; i < 1024; i += 256) {
        float4 v = xs[i];
        sm += (v.x + v.y) + (v.z + v.w);
        sq += v.x * v.x + v.y * v.y + v.z * v.z + v.w * v.w;
    }
    __shared__ float s1[256], s2[256];
    s1[tid] = sm; s2[tid] = sq;
    __syncthreads();
    for (int off = 128; off; off >>= 1) {
        if (tid < off) { s1[tid] += s1[tid + off]; s2[tid] += s2[tid + off]; }
        __syncthreads();
    }
    if (tid == 0) g_gnp[t][g][s] = make_float2(s1[0], s2[0]);
}

// ---------------------------------------------------------------------------
// QKV projection (HMMA) with fused GroupNorm apply; also preconverts outproj W.
// grid (32 hw-tiles of 128, 3 o-tiles of 128, 2 t), 256 threads.
// ---------------------------------------------------------------------------
__global__ void __launch_bounds__(256) qkv_kernel(const float* __restrict__ xA,
                                                  const float* __restrict__ xB,
                                                  const float* __restrict__ gw,
                                                  const float* __restrict__ gb,
                                                  const float* __restrict__ wA,
                                                  const float* __restrict__ wB,
                                                  const float* __restrict__ owA,
                                                  const float* __restrict__ owB) {
    extern __shared__ __half qsm[];
    __half* Ws = qsm;                 // [128][136]
    __half* Xs = qsm + 128 * 136;     // [128][136]
    __shared__ float scs[128], sbs[128];
    int t = blockIdx.z;
    const float* X = t ? xB : xA;
    const float* W = t ? wB : wA;
    __half* Y = g_qkv[t];
    int o0 = blockIdx.y * 128, hw0 = blockIdx.x * 128;
    int tid = threadIdx.x, wid = tid >> 5, L = tid & 31;

    // per-channel GN scale/bias from gnA partials
    if (tid < 128) {
        int c = tid, g = c >> 3;
        float sm = 0.f, sq = 0.f;
#pragma unroll
        for (int p = 0; p < 8; p++) {
            float2 v = g_gnp[t][g][p];
            sm += v.x; sq += v.y;
        }
        float mu  = sm * (1.f / 32768.f);
        float var = sq * (1.f / 32768.f) - mu * mu;
        float inv = rsqrtf(var + 1e-5f);
        float sc = inv * gw[c];
        scs[c] = sc;
        sbs[c] = gb[c] - mu * sc;
    }
    __syncthreads();

#pragma unroll
    for (int u = 0; u < 8; u++) {
        int idx = tid + 256 * u;         // 2048 = 128 rows x 16 chunks of 8
        int row = idx >> 4, c8 = (idx & 15) * 8;
        float4 f0 = *(const float4*)&W[(o0 + row) * 128 + c8];
        float4 f1 = *(const float4*)&W[(o0 + row) * 128 + c8 + 4];
        __half2 h0 = __floats2half2_rn(f0.x, f0.y);
        __half2 h1 = __floats2half2_rn(f0.z, f0.w);
        __half2 h2 = __floats2half2_rn(f1.x, f1.y);
        __half2 h3 = __floats2half2_rn(f1.z, f1.w);
        uint4 u4 = make_uint4(*(uint32_t*)&h0, *(uint32_t*)&h1, *(uint32_t*)&h2, *(uint32_t*)&h3);
        *(uint4*)&Ws[row * 136 + c8] = u4;
    }
#pragma unroll
    for (int u = 0; u < 8; u++) {
        int idx = tid + 256 * u;
        int row = idx >> 4, c8 = (idx & 15) * 8;
        float sc = scs[row], bb = sbs[row];
        const float* xp = X + row * HW + hw0 + c8;
        float4 f0 = *(const float4*)xp;
        float4 f1 = *(const float4*)(xp + 4);
        f0.x = f0.x * sc + bb; f0.y = f0.y * sc + bb;
        f0.z = f0.z * sc + bb; f0.w = f0.w * sc + bb;
        f1.x = f1.x * sc + bb; f1.y = f1.y * sc + bb;
        f1.z = f1.z * sc + bb; f1.w = f1.w * sc + bb;
        if (blockIdx.y == 0) {
            float* xp2 = g_xn[t] + row * HW + hw0 + c8;
            *(float4*)xp2 = f0;
            *(float4*)(xp2 + 4) = f1;
        }
        __half2 h0 = __floats2half2_rn(f0.x, f0.y);
        __half2 h1 = __floats2half2_rn(f0.z, f0.w);
        __half2 h2 = __floats2half2_rn(f1.x, f1.y);
        __half2 h3 = __floats2half2_rn(f1.z, f1.w);
        uint4 u4 = make_uint4(*(uint32_t*)&h0, *(uint32_t*)&h1, *(uint32_t*)&h2, *(uint32_t*)&h3);
        *(uint4*)&Xs[row * 136 + c8] = u4;
    }
    // two blocks also preconvert the outproj weights to fp16 for later
    if (blockIdx.y == 1 && blockIdx.x == 0) {
        const float* OW = t ? owB : owA;
        for (int i = tid; i < 4096; i += 256) {        // 4096 float4 = 16384 floats
            float4 f = *(const float4*)&OW[i * 4];
            __half2 h0 = __floats2half2_rn(f.x, f.y);
            __half2 h1 = __floats2half2_rn(f.z, f.w);
            *(uint2*)&g_wh[t][i * 4] = make_uint2(*(uint32_t*)&h0, *(uint32_t*)&h1);
        }
    }
    __syncthreads();

    int wr = wid & 3, wc = wid >> 2;
    uint32_t abase = s2u(Ws) + ((32 * wr + (L & 15)) * 136 + ((L >> 4) & 1) * 8) * 2;
    uint32_t bbase = s2u(Xs) + (((L & 7) + ((L >> 3) & 1) * 8) * 136 + 64 * wc + ((L >> 4) & 1) * 8) * 2;
    float acc[2][8][4] = {};
#pragma unroll
    for (int kk = 0; kk < 8; kk++) {
        uint32_t a0[4], a1[4];
        LDSM_N(a0, abase + (16 * kk) * 2);
        LDSM_N(a1, abase + (16 * 136 + 16 * kk) * 2);
        uint32_t bfr[4][4];
#pragma unroll
        for (int nn = 0; nn < 4; nn++)
            LDSM_T(bfr[nn], bbase + (16 * kk * 136 + 16 * nn) * 2);
#pragma unroll
        for (int nn = 0; nn < 4; nn++) {
            mma16816(acc[0][2 * nn],     a0, bfr[nn][0], bfr[nn][1]);
            mma16816(acc[0][2 * nn + 1], a0, bfr[nn][2], bfr[nn][3]);
            mma16816(acc[1][2 * nn],     a1, bfr[nn][0], bfr[nn][1]);
            mma16816(acc[1][2 * nn + 1], a1, bfr[nn][2], bfr[nn][3]);
        }
    }
#pragma unroll
    for (int mi = 0; mi < 2; mi++) {
        int row = o0 + 32 * wr + 16 * mi + (L >> 2);
        int row8 = row + 8;
        float s0 = ((row % 96) < 32) ? QSCALE : 1.f;
        float s1 = ((row8 % 96) < 32) ? QSCALE : 1.f;
#pragma unroll
        for (int nb = 0; nb < 8; nb++) {
            int col = hw0 + 64 * wc + 8 * nb + 2 * (L & 3);
            __half2 p0 = __floats2half2_rn(acc[mi][nb][0] * s0, acc[mi][nb][1] * s0);
            __half2 p1 = __floats2half2_rn(acc[mi][nb][2] * s1, acc[mi][nb][3] * s1);
            *(__half2*)&Y[row * HW + col] = p0;
            *(__half2*)&Y[row8 * HW + col] = p1;
        }
    }
}

// ---------------------------------------------------------------------------
// Cross-attention (HMMA). BM=64, 128 threads = 4 warps, grid (64 i-tiles, 8).
// 39.4KB static smem -> 4-5 CTAs/SM for cross-CTA latency hiding.
// S-MMA in fp16 accum (C frag == P A-frag), ex2 in place, rowsum via ones-MMA.
// ---------------------------------------------------------------------------
__device__ __forceinline__ void cp_issue(const __half* Kb, const __half* Vb, int j0,
                                         int buf, int tid, uint32_t ks, uint32_t vs) {
#pragma unroll
    for (int r = 0; r < 8; r++) {
        int idx = tid + 128 * r;            // 1024 chunks of 16B
        int mat = idx >> 9, wi = idx & 511;
        int dd = wi >> 4, c = wi & 15;
        const __half* src = (mat ? Vb : Kb) + dd * HW + j0 + c * 8;
        uint32_t dst = (mat ? vs : ks) + buf * 8704 + dd * 272 + c * 16;
        CP16(dst, src);
    }
    asm volatile("cp.async.commit_group;" ::: "memory");
}

__global__ void __launch_bounds__(128, 4) attn_kernel() {
    __shared__ __align__(16) __half Qs[32][72];       // [d][i] 64 cols
    __shared__ __align__(16) __half Ks[2][32][136];   // [buf][d][j] 128 cols
    __shared__ __align__(16) __half Vs[2][32][136];

    const int tid = threadIdx.x, wid = tid >> 5, L = tid & 31;
    const int ib = blockIdx.x, hd = blockIdx.y;
    const int dir = hd >> 2, h = hd & 3;
    const __half* Qb = g_qkv[dir ^ 1] + (h * 96 + 0) * HW;   // Q from the other stream
    const __half* Kb = g_qkv[dir]     + (h * 96 + 32) * HW;
    const __half* Vb = g_qkv[dir]     + (h * 96 + 64) * HW;
    __half* Ob = g_o[dir] + (h * 32) * HW;
    const int i0 = ib * 64;

    const uint32_t ksmem = s2u(&Ks[0][0][0]);
    const uint32_t vsmem = s2u(&Vs[0][0][0]);
    cp_issue(Kb, Vb, 0, 0, tid, ksmem, vsmem);

    // stage Q tile [32 d][64 i]
#pragma unroll
    for (int r = 0; r < 2; r++) {
        int idx = tid + 128 * r;          // 256 chunks
        int dd = idx >> 3, c = idx & 7;
        *(uint4*)&Qs[dd][c * 8] = *(const uint4*)(Qb + dd * HW + i0 + c * 8);
    }
    __syncthreads();

    // hoist Q A-fragments (rows 16*wid..+15, k = d)
    uint32_t qa[2][4];
#pragma unroll
    for (int s = 0; s < 2; s++) {
        int d_ = 16 * s + (L & 7) + ((L >> 4) & 1) * 8;
        int ii = 16 * wid + ((L >> 3) & 1) * 8;
        LDSM_T(qa[s], s2u(&Qs[d_][ii]));
    }

    // hoisted per-lane smem bases (bytes)
    const uint32_t kb0 = ksmem + ((L & 7) + ((L >> 3) & 1) * 8) * 272 + ((L >> 4) & 1) * 16;
    const uint32_t vb0 = vsmem + ((L & 7) + ((L >> 4) & 1) * 8) * 272 + ((L >> 3) & 1) * 16;
    const uint32_t ONES = (L < 4) ? 0x3C003C00u : 0u;   // ones col (n=0) B-fragment

    float oacc[4][4] = {};
    float racc[4] = {};     // rowsum accumulator (col 0 of ones-MMA)

#define ATTN_SUB(KB, VB, N0) do {                                                   \
        uint32_t sh[8][2] = {};                                                     \
        _Pragma("unroll")                                                           \
        for (int s = 0; s < 2; s++) {                                               \
            _Pragma("unroll")                                                       \
            for (int p = 0; p < 4; p++) {                                           \
                uint32_t kf[4];                                                     \
                LDSM_T(kf, (KB) + (16 * s) * 272 + (N0) * 2 + p * 32);              \
                mma16816h(sh[2 * p],     qa[s], kf[0], kf[1]);                      \
                mma16816h(sh[2 * p + 1], qa[s], kf[2], kf[3]);                      \
            }                                                                       \
        }                                                                           \
        _Pragma("unroll")                                                           \
        for (int u = 0; u < 8; u++) {                                               \
            asm("ex2.approx.f16x2 %0, %0;" : "+r"(sh[u][0]));                       \
            asm("ex2.approx.f16x2 %0, %0;" : "+r"(sh[u][1]));                       \
        }                                                                           \
        _Pragma("unroll")                                                           \
        for (int ks2 = 0; ks2 < 4; ks2++) {                                         \
            uint32_t pa[4] = {sh[2*ks2][0], sh[2*ks2][1], sh[2*ks2+1][0], sh[2*ks2+1][1]}; \
            _Pragma("unroll")                                                       \
            for (int q = 0; q < 2; q++) {                                           \
                uint32_t vv[4];                                                     \
                LDSM_N(vv, (VB) + (16 * q) * 272 + (N0) * 2 + ks2 * 32);            \
                mma16816(oacc[2 * q],     pa, vv[0], vv[1]);                        \
                mma16816(oacc[2 * q + 1], pa, vv[2], vv[3]);                        \
            }                                                                       \
            mma16816(racc, pa, ONES, ONES);                                         \
        }                                                                           \
    } while (0)

    for (int st = 0; st < 32; st++) {
        const int buf = st & 1;
        if (st < 31) {
            cp_issue(Kb, Vb, (st + 1) * 128, buf ^ 1, tid, ksmem, vsmem);
            asm volatile("cp.async.wait_group 1;" ::: "memory");
        } else {
            asm volatile("cp.async.wait_group 0;" ::: "memory");
        }
        __syncthreads();
        const uint32_t kb = kb0 + buf * 8704;
        const uint32_t vb = vb0 + buf * 8704;
        ATTN_SUB(kb, vb, 0);
        ATTN_SUB(kb, vb, 64);
        __syncthreads();
    }
#undef ATTN_SUB

    // rowsums live in lane (L & ~3) of each quad: c0 = row L/4, c2 = row L/4+8
    float rs0 = __shfl_sync(0xffffffffu, racc[0], L & ~3);
    float rs1 = __shfl_sync(0xffffffffu, racc[2], L & ~3);
    float inv0 = 1.f / rs0, inv1 = 1.f / rs1;

    // stage normalized O (fp16) into smem [d][i] (overlay Ks), coalesced store
    __half* Osm = (__half*)&Ks[0][0][0];   // use pitch 72: 32*72 halves fits
#pragma unroll
    for (int u = 0; u < 4; u++) {
        int d_ = 8 * u + 2 * (L & 3);
        int r = 16 * wid + (L >> 2);
        Osm[d_ * 72 + r]             = __float2half(oacc[u][0] * inv0);
        Osm[(d_ + 1) * 72 + r]       = __float2half(oacc[u][1] * inv0);
        Osm[d_ * 72 + r + 8]         = __float2half(oacc[u][2] * inv1);
        Osm[(d_ + 1) * 72 + r + 8]   = __float2half(oacc[u][3] * inv1);
    }
    __syncthreads();
#pragma unroll
    for (int u = 0; u < 2; u++) {
        int idx = tid + 128 * u;         // 256 = 32 rows x 8 chunks
        int dd = idx >> 3, c = idx & 7;
        uint4 v = *(uint4*)&Osm[dd * 72 + c * 8];
        *(uint4*)&Ob[dd * HW + i0 + c * 8] = v;
    }
}

// ---------------------------------------------------------------------------
// Out projection (HMMA) + bias + residual(f32). grid (64 hw-tiles of 64, 2 t).
// W preconverted fp16; W and O staged via cp.async (no register round-trip).
// ---------------------------------------------------------------------------
__global__ void __launch_bounds__(256) outproj_kernel(const float* __restrict__ bA,
                                                      const float* __restrict__ bB,
                                                      float* __restrict__ out) {
    extern __shared__ __half osm[];
    __half* Ws = osm;                // [128][136]
    __half* Os = osm + 128 * 136;    // [128][72]
    __shared__ float bs[128];
    int t = blockIdx.y;
    const float* bias = t ? bB : bA;
    const __half* Wh = g_wh[t];
    const __half* O = g_o[t];
    const float* res = g_xn[t];
    float* Y = out + t * (NC * HW);
    int hw0 = blockIdx.x * 64;
    int tid = threadIdx.x, wid = tid >> 5, L = tid & 31;

    uint32_t wsb = s2u(Ws), osb = s2u(Os);
#pragma unroll
    for (int u = 0; u < 8; u++) {
        int idx = tid + 256 * u;         // 2048 chunks: W 128x128 halves
        int row = idx >> 4, c8 = (idx & 15) * 8;
        CP16(wsb + (row * 136 + c8) * 2, Wh + row * 128 + c8);
    }
#pragma unroll
    for (int u = 0; u < 4; u++) {
        int idx = tid + 256 * u;         // 1024 chunks: O 128x64 halves
        int row = idx >> 3, c8 = (idx & 7) * 8;
        CP16(osb + (row * 72 + c8) * 2, O + row * HW + hw0 + c8);
    }
    asm volatile("cp.async.commit_group;" ::: "memory");
    if (tid < 128) bs[tid] = bias[tid];
    asm volatile("cp.async.wait_group 0;" ::: "memory");
    __syncthreads();

    int wr = wid & 3, wc = wid >> 2;
    uint32_t abase = wsb + ((32 * wr + (L & 15)) * 136 + ((L >> 4) & 1) * 8) * 2;
    uint32_t bbase = osb + (((L & 7) + ((L >> 3) & 1) * 8) * 72 + 32 * wc + ((L >> 4) & 1) * 8) * 2;
    float acc[2][4][4] = {};
#pragma unroll
    for (int kk = 0; kk < 8; kk++) {
        uint32_t a0[4], a1[4];
        LDSM_N(a0, abase + (16 * kk) * 2);
        LDSM_N(a1, abase + (16 * 136 + 16 * kk) * 2);
        uint32_t bfr[2][4];
#pragma unroll
        for (int nn = 0; nn < 2; nn++)
            LDSM_T(bfr[nn], bbase + (16 * kk * 72 + 16 * nn) * 2);
#pragma unroll
        for (int nn = 0; nn < 2; nn++) {
            mma16816(acc[0][2 * nn],     a0, bfr[nn][0], bfr[nn][1]);
            mma16816(acc[0][2 * nn + 1], a0, bfr[nn][2], bfr[nn][3]);
            mma16816(acc[1][2 * nn],     a1, bfr[nn][0], bfr[nn][1]);
            mma16816(acc[1][2 * nn + 1], a1, bfr[nn][2], bfr[nn][3]);
        }
    }
#pragma unroll
    for (int mi = 0; mi < 2; mi++) {
        int row = 32 * wr + 16 * mi + (L >> 2);
#pragma unroll
        for (int nb = 0; nb < 4; nb++) {
            int col = hw0 + 32 * wc + 8 * nb + 2 * (L & 3);
            float2 r0 = *(const float2*)&res[row * HW + col];
            float2 v0;
            v0.x = acc[mi][nb][0] + bs[row] + r0.x;
            v0.y = acc[mi][nb][1] + bs[row] + r0.y;
            *(float2*)&Y[row * HW + col] = v0;
            float2 r1 = *(const float2*)&res[(row + 8) * HW + col];
            float2 v1;
            v1.x = acc[mi][nb][2] + bs[row + 8] + r1.x;
            v1.y = acc[mi][nb][3] + bs[row + 8] + r1.y;
            *(float2*)&Y[(row + 8) * HW + col] = v1;
        }
    }
}

// ---------------------------------------------------------------------------
extern "C" void kernel_launch(void* const* d_in, const int* in_sizes, int n_in,
                              void* d_out, int out_size) {
    const float* xA    = (const float*)d_in[0];
    const float* xB    = (const float*)d_in[1];
    const float* gnw   = (const float*)d_in[2];
    const float* gnb   = (const float*)d_in[3];
    const float* qkvAw = (const float*)d_in[4];
    const float* outAw = (const float*)d_in[5];
    const float* outAb = (const float*)d_in[6];
    const float* qkvBw = (const float*)d_in[7];
    const float* outBw = (const float*)d_in[8];
    const float* outBb = (const float*)d_in[9];
    float* out = (float*)d_out;

    const int QKV_SMEM = 2 * 128 * 136 * 2;            // 69632
    const int OUT_SMEM = 128 * 136 * 2 + 128 * 72 * 2; // 53248
    cudaFuncSetAttribute(qkv_kernel, cudaFuncAttributeMaxDynamicSharedMemorySize, QKV_SMEM);
    cudaFuncSetAttribute(outproj_kernel, cudaFuncAttributeMaxDynamicSharedMemorySize, OUT_SMEM);

    gnA_kernel<<<dim3(16, 8, 2), 256>>>(xA, xB);
    qkv_kernel<<<dim3(32, 3, 2), 256, QKV_SMEM>>>(xA, xB, gnw, gnb, qkvAw, qkvBw, outAw, outBw);
    attn_kernel<<<dim3(64, 8), 128>>>();
    outproj_kernel<<<dim3(64, 2), 256, OUT_SMEM>>>(outAb, outBb, out);
}

// round 9
// speedup vs baseline: 1.0611x; 1.0611x over previous
#include <cuda_runtime.h>
#include <cuda_fp16.h>
#include <cstdint>
#include <math.h>

#define HW 4096
#define NC 128

// Scratch (static device memory — no allocations allowed)
__device__ float  g_xn[2][NC * HW];        // normalized inputs (residual), fp32
__device__ __half g_qwh[2][3 * NC * NC];   // qkv weights fp16 [384][128]
__device__ __half g_owh[2][NC * NC];       // outproj weights fp16 [128][128]
__device__ __half g_qkv[2][3 * NC * HW];   // qkv projections, fp16 (Q prescaled)
__device__ __half g_o[2][NC * HW];         // attention outputs, fp16
__device__ float2 g_gnp[2][16][8];         // groupnorm partial sums

// 1/sqrt(128) * log2(e): folded into Q so softmax is a bare ex2
#define QSCALE (0.08838834764831845f * 1.4426950408889634f)

// ---------------------------------------------------------------------------
__device__ __forceinline__ uint32_t s2u(const void* p) {
    uint32_t a;
    asm("{ .reg .u64 t; cvta.to.shared.u64 t, %1; cvt.u32.u64 %0, t; }" : "=r"(a) : "l"(p));
    return a;
}
__device__ __forceinline__ void mma16816(float* c, const uint32_t* a, uint32_t b0, uint32_t b1) {
    asm volatile(
        "mma.sync.aligned.m16n8k16.row.col.f32.f16.f16.f32 "
        "{%0,%1,%2,%3}, {%4,%5,%6,%7}, {%8,%9}, {%0,%1,%2,%3};"
        : "+f"(c[0]), "+f"(c[1]), "+f"(c[2]), "+f"(c[3])
        : "r"(a[0]), "r"(a[1]), "r"(a[2]), "r"(a[3]), "r"(b0), "r"(b1));
}
// fp16-accumulate: C fragment {c0c1},{c2c3} == P A-fragment packing
__device__ __forceinline__ void mma16816h(uint32_t* c, const uint32_t* a, uint32_t b0, uint32_t b1) {
    asm volatile(
        "mma.sync.aligned.m16n8k16.row.col.f16.f16.f16.f16 "
        "{%0,%1}, {%2,%3,%4,%5}, {%6,%7}, {%0,%1};"
        : "+r"(c[0]), "+r"(c[1])
        : "r"(a[0]), "r"(a[1]), "r"(a[2]), "r"(a[3]), "r"(b0), "r"(b1));
}
#define LDSM_T(r, p) \
    asm volatile("ldmatrix.sync.aligned.m8n8.x4.trans.shared.b16 {%0,%1,%2,%3}, [%4];" \
        : "=r"((r)[0]), "=r"((r)[1]), "=r"((r)[2]), "=r"((r)[3]) : "r"(p))
#define LDSM_N(r, p) \
    asm volatile("ldmatrix.sync.aligned.m8n8.x4.shared.b16 {%0,%1,%2,%3}, [%4];" \
        : "=r"((r)[0]), "=r"((r)[1]), "=r"((r)[2]), "=r"((r)[3]) : "r"(p))
#define CP16(dst, src) \
    asm volatile("cp.async.cg.shared.global [%0], [%1], 16;" :: "r"(dst), "l"(src))

// ---------------------------------------------------------------------------
// GroupNorm pass A: partial sums + fp16 weight preconversion.
// grid (16 g, 8 s, 2 t), 256 threads.
// ---------------------------------------------------------------------------
__global__ void gnA_kernel(const float* __restrict__ xA, const float* __restrict__ xB,
                           const float* __restrict__ qwA, const float* __restrict__ qwB,
                           const float* __restrict__ owA, const float* __restrict__ owB) {
    int g = blockIdx.x, s = blockIdx.y, t = blockIdx.z, tid = threadIdx.x;

    // weight conversion: 65536 float2's over 65536 threads
    {
        int flat = ((blockIdx.z * 8 + blockIdx.y) * 16 + blockIdx.x) * 256 + tid;
        const float* src; __half* dst; int i;
        if (flat < 49152) {
            int tt = flat / 24576; i = flat % 24576;
            src = tt ? qwB : qwA; dst = g_qwh[tt];
        } else {
            int r = flat - 49152; int tt = r / 8192; i = r % 8192;
            src = tt ? owB : owA; dst = g_owh[tt];
        }
        float2 f = *(const float2*)&src[i * 2];
        __half2 h = __floats2half2_rn(f.x, f.y);
        *(uint32_t*)&dst[i * 2] = *(uint32_t*)&h;
    }

    const float4* xs = (const float4*)((t ? xB : xA) + g * 32768 + s * 4096);
    float sm = 0.f, sq = 0.f;
    for (int i = tid; i < 1024; i += 256) {
        float4 v = xs[i];
        sm += (v.x + v.y) + (v.z + v.w);
        sq += v.x * v.x + v.y * v.y + v.z * v.z + v.w * v.w;
    }
    __shared__ float s1[256], s2[256];
    s1[tid] = sm; s2[tid] = sq;
    __syncthreads();
    for (int off = 128; off; off >>= 1) {
        if (tid < off) { s1[tid] += s1[tid + off]; s2[tid] += s2[tid + off]; }
        __syncthreads();
    }
    if (tid == 0) g_gnp[t][g][s] = make_float2(s1[0], s2[0]);
}

// ---------------------------------------------------------------------------
// QKV projection (HMMA) + fused GroupNorm apply. W fp16 via cp.async.
// grid (64 hw-tiles of 64, 3 o-tiles of 128, 2 t), 256 threads.
// ---------------------------------------------------------------------------
__global__ void __launch_bounds__(256) qkv_kernel(const float* __restrict__ xA,
                                                  const float* __restrict__ xB,
                                                  const float* __restrict__ gw,
                                                  const float* __restrict__ gb) {
    extern __shared__ char qraw[];
    __half* Ws = (__half*)qraw;              // [128][136]
    __half* Xs = (__half*)(qraw + 34816);    // [128][72]
    __shared__ float scs[128], sbs[128];
    int t = blockIdx.z;
    const float* X = t ? xB : xA;
    __half* Y = g_qkv[t];
    int o0 = blockIdx.y * 128, hw0 = blockIdx.x * 64;
    int tid = threadIdx.x, wid = tid >> 5, L = tid & 31;
    uint32_t wsb = s2u(Ws), xsb = s2u(Xs);

    // W via cp.async (fp16 preconverted)
#pragma unroll
    for (int u = 0; u < 8; u++) {
        int idx = tid + 256 * u;         // 2048 chunks
        int row = idx >> 4, c8 = (idx & 15) * 8;
        CP16(wsb + (row * 136 + c8) * 2, g_qwh[t] + (o0 + row) * 128 + c8);
    }
    asm volatile("cp.async.commit_group;" ::: "memory");

    // per-channel GN scale/bias from gnA partials
    if (tid < 128) {
        int c = tid, g = c >> 3;
        float sm = 0.f, sq = 0.f;
#pragma unroll
        for (int p = 0; p < 8; p++) {
            float2 v = g_gnp[t][g][p];
            sm += v.x; sq += v.y;
        }
        float mu  = sm * (1.f / 32768.f);
        float var = sq * (1.f / 32768.f) - mu * mu;
        float inv = rsqrtf(var + 1e-5f);
        float sc = inv * gw[c];
        scs[c] = sc;
        sbs[c] = gb[c] - mu * sc;
    }
    __syncthreads();

    // X tile [128 ch][64 hw]: load, normalize, cvt; write residual (by==0)
#pragma unroll
    for (int u = 0; u < 8; u++) {
        int idx = tid + 256 * u;         // 2048 chunks of 4 floats
        int row = idx >> 4, c4 = (idx & 15) * 4;
        float sc = scs[row], bb = sbs[row];
        float4 f = *(const float4*)&X[row * HW + hw0 + c4];
        f.x = f.x * sc + bb; f.y = f.y * sc + bb;
        f.z = f.z * sc + bb; f.w = f.w * sc + bb;
        if (blockIdx.y == 0)
            *(float4*)&g_xn[t][row * HW + hw0 + c4] = f;
        __half2 h0 = __floats2half2_rn(f.x, f.y);
        __half2 h1 = __floats2half2_rn(f.z, f.w);
        *(uint2*)&Xs[row * 72 + c4] = make_uint2(*(uint32_t*)&h0, *(uint32_t*)&h1);
    }
    asm volatile("cp.async.wait_group 0;" ::: "memory");
    __syncthreads();

    int wr = wid & 3, wc = wid >> 2;     // 8 warps: 4 row-groups x 2 col-groups
    uint32_t abase = wsb + ((32 * wr + (L & 15)) * 136 + ((L >> 4) & 1) * 8) * 2;
    uint32_t bbase = xsb + (((L & 7) + ((L >> 3) & 1) * 8) * 72 + 32 * wc + ((L >> 4) & 1) * 8) * 2;
    float acc[2][4][4] = {};
#pragma unroll
    for (int kk = 0; kk < 8; kk++) {
        uint32_t a0[4], a1[4];
        LDSM_N(a0, abase + (16 * kk) * 2);
        LDSM_N(a1, abase + (16 * 136 + 16 * kk) * 2);
        uint32_t bfr[2][4];
#pragma unroll
        for (int nn = 0; nn < 2; nn++)
            LDSM_T(bfr[nn], bbase + (16 * kk * 72 + 16 * nn) * 2);
#pragma unroll
        for (int nn = 0; nn < 2; nn++) {
            mma16816(acc[0][2 * nn],     a0, bfr[nn][0], bfr[nn][1]);
            mma16816(acc[0][2 * nn + 1], a0, bfr[nn][2], bfr[nn][3]);
            mma16816(acc[1][2 * nn],     a1, bfr[nn][0], bfr[nn][1]);
            mma16816(acc[1][2 * nn + 1], a1, bfr[nn][2], bfr[nn][3]);
        }
    }
#pragma unroll
    for (int mi = 0; mi < 2; mi++) {
        int row = o0 + 32 * wr + 16 * mi + (L >> 2);
        int row8 = row + 8;
        float s0 = ((row % 96) < 32) ? QSCALE : 1.f;
        float s1 = ((row8 % 96) < 32) ? QSCALE : 1.f;
#pragma unroll
        for (int nb = 0; nb < 4; nb++) {
            int col = hw0 + 32 * wc + 8 * nb + 2 * (L & 3);
            __half2 p0 = __floats2half2_rn(acc[mi][nb][0] * s0, acc[mi][nb][1] * s0);
            __half2 p1 = __floats2half2_rn(acc[mi][nb][2] * s1, acc[mi][nb][3] * s1);
            *(__half2*)&Y[row * HW + col] = p0;
            *(__half2*)&Y[row8 * HW + col] = p1;
        }
    }
}

// ---------------------------------------------------------------------------
// Cross-attention (HMMA). BM=128, 128 threads = 4 warps x 32 rows each.
// grid (32 i-tiles, 8 = dir*4+head). 3-buffer KV ring, prefetch depth 2,
// ONE __syncthreads per stage. Phased: all S-MMAs -> all ex2 -> all O-MMAs.
// ---------------------------------------------------------------------------
#define QS_SZ 8704            // Q [32][136] halves
#define BUF_SZ 17408          // K[32][136] + V[32][136]

__device__ __forceinline__ void attn_cp(const __half* Kb, const __half* Vb, int j0,
                                        uint32_t bufb, int tid) {
#pragma unroll
    for (int r = 0; r < 8; r++) {
        int idx = tid + 128 * r;            // 1024 chunks of 16B
        int mat = idx >> 9, wi = idx & 511;
        int dd = wi >> 4, c = wi & 15;
        const __half* src = (mat ? Vb : Kb) + dd * HW + j0 + c * 8;
        CP16(bufb + mat * 8704 + dd * 272 + c * 16, src);
    }
    asm volatile("cp.async.commit_group;" ::: "memory");
}

__global__ void __launch_bounds__(128) attn_kernel() {
    extern __shared__ char araw[];
    const uint32_t qsb = s2u(araw);
    const uint32_t bufb0 = qsb + QS_SZ;

    const int tid = threadIdx.x, wid = tid >> 5, L = tid & 31;
    const int ib = blockIdx.x, hd = blockIdx.y;
    const int dir = hd >> 2, h = hd & 3;
    const __half* Qb = g_qkv[dir ^ 1] + (h * 96 + 0) * HW;   // Q from the other stream
    const __half* Kb = g_qkv[dir]     + (h * 96 + 32) * HW;
    const __half* Vb = g_qkv[dir]     + (h * 96 + 64) * HW;
    __half* Ob = g_o[dir] + (h * 32) * HW;
    const int i0 = ib * 128;

    attn_cp(Kb, Vb, 0, bufb0, tid);
    attn_cp(Kb, Vb, 128, bufb0 + BUF_SZ, tid);

    // stage Q tile [32 d][128 i]
    __half* Qs = (__half*)araw;
#pragma unroll
    for (int r = 0; r < 4; r++) {
        int idx = tid + 128 * r;          // 512 chunks
        int dd = idx >> 4, c = idx & 15;
        *(uint4*)&Qs[dd * 136 + c * 8] = *(const uint4*)(Qb + dd * HW + i0 + c * 8);
    }
    __syncthreads();

    // hoist Q A-fragments: warp rows 32*wid + 16*m
    uint32_t qa[2][2][4];
#pragma unroll
    for (int m = 0; m < 2; m++)
#pragma unroll
        for (int s = 0; s < 2; s++) {
            int d_ = 16 * s + (L & 7) + ((L >> 4) & 1) * 8;
            int ii = 32 * wid + 16 * m + ((L >> 3) & 1) * 8;
            LDSM_T(qa[m][s], qsb + (d_ * 136 + ii) * 2);
        }

    const uint32_t klane = ((L & 7) + ((L >> 3) & 1) * 8) * 272 + ((L >> 4) & 1) * 16;
    const uint32_t vlane = ((L & 7) + ((L >> 4) & 1) * 8) * 272 + ((L >> 3) & 1) * 16;
    const uint32_t ONES = (L < 4) ? 0x3C003C00u : 0u;   // ones col (n=0) B-fragment

    float oacc[2][4][4] = {};
    float racc[2][4] = {};

    for (int st = 0; st < 32; st++) {
        if (st < 31) { asm volatile("cp.async.wait_group 1;" ::: "memory"); }
        else         { asm volatile("cp.async.wait_group 0;" ::: "memory"); }
        __syncthreads();
        if (st < 30) attn_cp(Kb, Vb, (st + 2) * 128, bufb0 + ((st + 2) % 3) * BUF_SZ, tid);

        const uint32_t bb = bufb0 + (st % 3) * BUF_SZ;
        const uint32_t kb = bb + klane;
        const uint32_t vb = bb + 8704 + vlane;

        // ---- phase 1: all S-MMAs (fp16 accum; C frag == P A-frag) ----
        uint32_t sh[2][2][8][2] = {};   // [sub][m][nb][half]
#pragma unroll
        for (int sub = 0; sub < 2; sub++)
#pragma unroll
            for (int s = 0; s < 2; s++)
#pragma unroll
                for (int p = 0; p < 4; p++) {
                    uint32_t kf[4];
                    LDSM_T(kf, kb + (16 * s) * 272 + sub * 128 + p * 32);
                    mma16816h(sh[sub][0][2 * p],     qa[0][s], kf[0], kf[1]);
                    mma16816h(sh[sub][0][2 * p + 1], qa[0][s], kf[2], kf[3]);
                    mma16816h(sh[sub][1][2 * p],     qa[1][s], kf[0], kf[1]);
                    mma16816h(sh[sub][1][2 * p + 1], qa[1][s], kf[2], kf[3]);
                }

        // ---- phase 2: exp2 in place ----
        {
            uint32_t* shp = &sh[0][0][0][0];
#pragma unroll
            for (int u = 0; u < 64; u++)
                asm("ex2.approx.f16x2 %0, %0;" : "+r"(shp[u]));
        }

        // ---- phase 3: all O-MMAs + rowsum MMA ----
#pragma unroll
        for (int sub = 0; sub < 2; sub++)
#pragma unroll
            for (int k2 = 0; k2 < 4; k2++) {
                uint32_t v0[4], v1[4];
                LDSM_N(v0, vb + sub * 128 + k2 * 32);
                LDSM_N(v1, vb + 16 * 272 + sub * 128 + k2 * 32);
#pragma unroll
                for (int m = 0; m < 2; m++) {
                    uint32_t pa[4] = {sh[sub][m][2 * k2][0], sh[sub][m][2 * k2][1],
                                      sh[sub][m][2 * k2 + 1][0], sh[sub][m][2 * k2 + 1][1]};
                    mma16816(oacc[m][0], pa, v0[0], v0[1]);
                    mma16816(oacc[m][1], pa, v0[2], v0[3]);
                    mma16816(oacc[m][2], pa, v1[0], v1[1]);
                    mma16816(oacc[m][3], pa, v1[2], v1[3]);
                    mma16816(racc[m],    pa, ONES, ONES);
                }
            }
    }

    // rowsums: lane (L & ~3) of each quad holds col 0
    float inv0[2], inv1[2];
#pragma unroll
    for (int m = 0; m < 2; m++) {
        inv0[m] = 1.f / __shfl_sync(0xffffffffu, racc[m][0], L & ~3);
        inv1[m] = 1.f / __shfl_sync(0xffffffffu, racc[m][2], L & ~3);
    }

    __syncthreads();
    // stage normalized O (fp16) into smem [d][i] (overlay buffer 0), store
    __half* Osm = (__half*)(araw + QS_SZ);    // 32*136 halves = 8704B
#pragma unroll
    for (int m = 0; m < 2; m++)
#pragma unroll
        for (int nb = 0; nb < 4; nb++) {
            int d_ = 8 * nb + 2 * (L & 3);
            int r = 32 * wid + 16 * m + (L >> 2);
            Osm[d_ * 136 + r]           = __float2half(oacc[m][nb][0] * inv0[m]);
            Osm[(d_ + 1) * 136 + r]     = __float2half(oacc[m][nb][1] * inv0[m]);
            Osm[d_ * 136 + r + 8]       = __float2half(oacc[m][nb][2] * inv1[m]);
            Osm[(d_ + 1) * 136 + r + 8] = __float2half(oacc[m][nb][3] * inv1[m]);
        }
    __syncthreads();
#pragma unroll
    for (int u = 0; u < 4; u++) {
        int idx = tid + 128 * u;         // 512 = 32 rows x 16 chunks
        int dd = idx >> 4, c = idx & 15;
        uint4 v = *(uint4*)&Osm[dd * 136 + c * 8];
        *(uint4*)&Ob[dd * HW + i0 + c * 8] = v;
    }
}

// ---------------------------------------------------------------------------
// Out projection (HMMA) + bias + residual. grid (64 hw, 2 row-halves, 2 t),
// 128 threads. W fp16 + O + residual all staged via cp.async.
// ---------------------------------------------------------------------------
__global__ void __launch_bounds__(128) outproj_kernel(const float* __restrict__ bA,
                                                      const float* __restrict__ bB,
                                                      float* __restrict__ out) {
    extern __shared__ char oraw[];
    uint32_t wsb = s2u(oraw);                       // W [64][136] halves
    uint32_t osb = wsb + 17408;                     // O [128][72] halves
    uint32_t rsb = osb + 18432;                     // res [64][64] f32
    float* Rs = (float*)(oraw + 17408 + 18432);
    __shared__ float bs[64];
    int t = blockIdx.z;
    const float* bias = t ? bB : bA;
    const __half* O = g_o[t];
    const float* res = g_xn[t];
    float* Y = out + t * (NC * HW);
    int row0 = blockIdx.y * 64, hw0 = blockIdx.x * 64;
    int tid = threadIdx.x, wid = tid >> 5, L = tid & 31;

#pragma unroll
    for (int u = 0; u < 8; u++) {
        int idx = tid + 128 * u;         // 1024 chunks: W 64 rows x 128 cols (FIXED)
        int row = idx >> 4, c8 = (idx & 15) * 8;
        CP16(wsb + (row * 136 + c8) * 2, g_owh[t] + (row0 + row) * 128 + c8);
    }
#pragma unroll
    for (int u = 0; u < 8; u++) {
        int idx = tid + 128 * u;         // 1024 chunks: O 128x64 halves
        int row = idx >> 3, c8 = (idx & 7) * 8;
        CP16(osb + (row * 72 + c8) * 2, O + row * HW + hw0 + c8);
    }
#pragma unroll
    for (int u = 0; u < 8; u++) {
        int idx = tid + 128 * u;         // 1024 chunks: res 64x64 f32
        int row = idx >> 4, c4 = (idx & 15) * 4;
        CP16(rsb + (row * 64 + c4) * 4, res + (row0 + row) * HW + hw0 + c4);
    }
    asm volatile("cp.async.commit_group;" ::: "memory");
    if (tid < 64) bs[tid] = bias[row0 + tid];
    asm volatile("cp.async.wait_group 0;" ::: "memory");
    __syncthreads();

    int wr = wid & 1, wc = wid >> 1;     // 4 warps: 2 row-groups x 2 col-groups
    uint32_t abase = wsb + ((32 * wr + (L & 15)) * 136 + ((L >> 4) & 1) * 8) * 2;
    uint32_t bbase = osb + (((L & 7) + ((L >> 3) & 1) * 8) * 72 + 32 * wc + ((L >> 4) & 1) * 8) * 2;
    float acc[2][4][4] = {};
#pragma unroll
    for (int kk = 0; kk < 8; kk++) {
        uint32_t a0[4], a1[4];
        LDSM_N(a0, abase + (16 * kk) * 2);
        LDSM_N(a1, abase + (16 * 136 + 16 * kk) * 2);
        uint32_t bfr[2][4];
#pragma unroll
        for (int nn = 0; nn < 2; nn++)
            LDSM_T(bfr[nn], bbase + (16 * kk * 72 + 16 * nn) * 2);
#pragma unroll
        for (int nn = 0; nn < 2; nn++) {
            mma16816(acc[0][2 * nn],     a0, bfr[nn][0], bfr[nn][1]);
            mma16816(acc[0][2 * nn + 1], a0, bfr[nn][2], bfr[nn][3]);
            mma16816(acc[1][2 * nn],     a1, bfr[nn][0], bfr[nn][1]);
            mma16816(acc[1][2 * nn + 1], a1, bfr[nn][2], bfr[nn][3]);
        }
    }
#pragma unroll
    for (int mi = 0; mi < 2; mi++) {
        int rl = 32 * wr + 16 * mi + (L >> 2);
#pragma unroll
        for (int nb = 0; nb < 4; nb++) {
            int cl = 32 * wc + 8 * nb + 2 * (L & 3);
            float2 r0 = *(float2*)&Rs[rl * 64 + cl];
            float2 v0;
            v0.x = acc[mi][nb][0] + bs[rl] + r0.x;
            v0.y = acc[mi][nb][1] + bs[rl] + r0.y;
            *(float2*)&Y[(row0 + rl) * HW + hw0 + cl] = v0;
            float2 r1 = *(float2*)&Rs[(rl + 8) * 64 + cl];
            float2 v1;
            v1.x = acc[mi][nb][2] + bs[rl + 8] + r1.x;
            v1.y = acc[mi][nb][3] + bs[rl + 8] + r1.y;
            *(float2*)&Y[(row0 + rl + 8) * HW + hw0 + cl] = v1;
        }
    }
}

// ---------------------------------------------------------------------------
extern "C" void kernel_launch(void* const* d_in, const int* in_sizes, int n_in,
                              void* d_out, int out_size) {
    const float* xA    = (const float*)d_in[0];
    const float* xB    = (const float*)d_in[1];
    const float* gnw   = (const float*)d_in[2];
    const float* gnb   = (const float*)d_in[3];
    const float* qkvAw = (const float*)d_in[4];
    const float* outAw = (const float*)d_in[5];
    const float* outAb = (const float*)d_in[6];
    const float* qkvBw = (const float*)d_in[7];
    const float* outBw = (const float*)d_in[8];
    const float* outBb = (const float*)d_in[9];
    float* out = (float*)d_out;

    const int QKV_SMEM  = 34816 + 18432;            // 53248
    const int ATTN_SMEM = QS_SZ + 3 * BUF_SZ;       // 60928
    const int OUT_SMEM  = 17408 + 18432 + 16384;    // 52224
    cudaFuncSetAttribute(qkv_kernel, cudaFuncAttributeMaxDynamicSharedMemorySize, QKV_SMEM);
    cudaFuncSetAttribute(attn_kernel, cudaFuncAttributeMaxDynamicSharedMemorySize, ATTN_SMEM);
    cudaFuncSetAttribute(outproj_kernel, cudaFuncAttributeMaxDynamicSharedMemorySize, OUT_SMEM);

    gnA_kernel<<<dim3(16, 8, 2), 256>>>(xA, xB, qkvAw, qkvBw, outAw, outBw);
    qkv_kernel<<<dim3(64, 3, 2), 256, QKV_SMEM>>>(xA, xB, gnw, gnb);
    attn_kernel<<<dim3(32, 8), 128, ATTN_SMEM>>>();
    outproj_kernel<<<dim3(64, 2, 2), 128, OUT_SMEM>>>(outAb, outBb, out);
}